// round 3
// baseline (speedup 1.0000x reference)
#include <cuda_runtime.h>

#define BB 1024
#define DD 64
#define FF 8
#define ZZ 72          // D + F
#define HH 256
#define TT 50
#define TUU 128
#define NSUB 4
#define ROWS 8
#define CTAS (BB/ROWS) // 128
#define NT 512
#define ZSTRIDE 576    // ZZ*ROWS floats per stage slot
#define HSTRIDE 288    // 256 + 8*4 skew floats per row

typedef unsigned long long u64;

__device__ __forceinline__ u64 fma2(u64 a, u64 b, u64 c) {
    u64 d;
    asm("fma.rn.f32x2 %0, %1, %2, %3;" : "=l"(d) : "l"(a), "l"(b), "l"(c));
    return d;
}
__device__ __forceinline__ u64 pack2(float lo, float hi) {
    u64 d;
    asm("mov.b64 %0, {%1, %2};" : "=l"(d) : "f"(lo), "f"(hi));
    return d;
}
__device__ __forceinline__ float2 unpack2(u64 v) {
    float lo, hi;
    asm("mov.b64 {%0, %1}, %2;" : "=f"(lo), "=f"(hi) : "l"(v));
    return make_float2(lo, hi);
}
// tanh(x) = 1 - 2/(exp(2x)+1) via ex2.approx + rcp.approx, abs err ~1e-6.
__device__ __forceinline__ float fast_tanh(float x) {
    float e, r;
    asm("ex2.approx.f32 %0, %1;" : "=f"(e) : "f"(x * 2.8853900817779268f));
    asm("rcp.approx.f32 %0, %1;" : "=f"(r) : "f"(e + 1.0f));
    return fmaf(-2.0f, r, 1.0f);
}

// SMEM floats:
//   ubuf  : 8*128*8      = 8192
//   zbuf  : 6*ZSTRIDE    = 3456   (per-stage z slots: x-part + u-part)
//   hbuf  : 8*HSTRIDE    = 2304   (skewed: col j at j + (j>>5)*4)
//   te 64, tu 128
#define SMEM_FLOATS (8192 + 6*ZSTRIDE + ROWS*HSTRIDE + 64 + 128)

__global__ void __launch_bounds__(NT, 1)
node_kernel(const float* __restrict__ x0g, const float* __restrict__ te_g,
            const float* __restrict__ tu_g, const float* __restrict__ u_g,
            const float* __restrict__ W1g, const float* __restrict__ b1g,
            const float* __restrict__ W2g, const float* __restrict__ b2g,
            float* __restrict__ out)
{
    extern __shared__ float sm[];
    float* ubuf = sm;                      // [ROWS][TUU][FF]
    float* zbuf = ubuf + 8192;             // [6][ROWS][ZZ]
    float* hbuf = zbuf + 6 * ZSTRIDE;      // [ROWS][HSTRIDE]
    float* te   = hbuf + ROWS * HSTRIDE;   // [64]
    float* tu   = te + 64;                 // [TUU]

    const int tid  = threadIdx.x;
    const int b0   = blockIdx.x * ROWS;
    const int lane = tid & 31;

    // ---- one-time loads ----
    for (int i = tid; i < TT;  i += NT) te[i] = te_g[i];
    for (int i = tid; i < TUU; i += NT) tu[i] = tu_g[i];
    for (int i = tid; i < ROWS * TUU * FF; i += NT) {
        int r = i / (TUU * FF);
        int o = i - r * (TUU * FF);
        ubuf[i] = u_g[(size_t)(b0 + r) * (TUU * FF) + o];
    }

    // Layer-1: lane pair (2j,2j+1) owns column j; half = low bit picks K-half.
    const int j    = tid >> 1;      // 0..255
    const int half = tid & 1;
    u64 w1p[18];
#pragma unroll
    for (int i = 0; i < 18; ++i)
        w1p[i] = pack2(W1g[(half * 36 + 2 * i) * HH + j],
                       W1g[(half * 36 + 2 * i + 1) * HH + j]);
    const float b1j = (half == 0) ? b1g[j] : 0.0f;   // bias in half-0 partial

    // Layer-2: pg = lane&7 (K-slice of 32), dcol = warp*4 + lane>>3.
    const int pg   = lane & 7;
    const int dcol = ((tid >> 5) << 2) | (lane >> 3);   // 0..63
    u64 w2p[16];
#pragma unroll
    for (int i = 0; i < 16; ++i)
        w2p[i] = pack2(W2g[(pg * 32 + 2 * i) * DD + dcol],
                       W2g[(pg * 32 + 2 * i + 1) * DD + dcol]);
    const float b2d = b2g[dcol];

    // Owner: thread owns state element (orr = pg, dcol). Covers 8x64 = 512.
    const int orr = pg;
    float xc = x0g[(size_t)(b0 + orr) * DD + dcol];
    out[(size_t)(b0 + orr) * (TT * DD) + dcol] = xc;     // t index 0
    float kk[6];
    __syncthreads();

    // Dopri5 tableau (fp32-rounded)
    const float A21 = 0.2f;
    const float A31 = 0.075f,                    A32 = 0.225f;
    const float A41 = (float)( 44.0/45.0),       A42 = (float)(-56.0/15.0),
                A43 = (float)( 32.0/9.0);
    const float A51 = (float)( 19372.0/6561.0),  A52 = (float)(-25360.0/2187.0),
                A53 = (float)( 64448.0/6561.0),  A54 = (float)(-212.0/729.0);
    const float A61 = (float)( 9017.0/3168.0),   A62 = (float)(-355.0/33.0),
                A63 = (float)( 46732.0/5247.0),  A64 = (float)( 49.0/176.0),
                A65 = (float)(-5103.0/18656.0);
    const float B1  = (float)( 35.0/384.0),      B3  = (float)(500.0/1113.0),
                B4  = (float)(125.0/192.0),      B5  = (float)(-2187.0/6784.0),
                B6  = (float)( 11.0/84.0);
    const float CST[6] = {0.0f, 0.2f, 0.3f, 0.8f, (float)(8.0/9.0), 1.0f};

    for (int ci = 0; ci < TT - 1; ++ci) {
        const float tc0 = te[ci];
        const float dtc = te[ci + 1] - tc0;
        const float dt  = dtc * 0.25f;
        for (int s = 0; s < NSUB; ++s) {
            const float tsub = tc0 + dtc * ((float)s * 0.25f);

            // ---- precompute u-interp for all 6 stages (exact searchsorted) ----
            if (tid < 6 * ROWS * FF) {                       // 384 threads
                int st = tid >> 6;
                int rr = (tid >> 3) & 7;
                int ff = tid & 7;
                float tst = tsub + CST[st] * dt;
                int idx = (int)floorf(tst * (float)(TUU - 1));
                idx = max(0, min(TUU - 2, idx));
                while (idx > 0 && tu[idx] > tst) --idx;
                while (idx < TUU - 2 && tu[idx + 1] <= tst) ++idx;
                float t0v = tu[idx], t1v = tu[idx + 1];
                float w = (tst - t0v) / (t1v - t0v);
                float u0v = ubuf[rr * (TUU * FF) + idx * FF + ff];
                float u1v = ubuf[rr * (TUU * FF) + (idx + 1) * FF + ff];
                zbuf[st * ZSTRIDE + rr * ZZ + DD + ff] = u0v + w * (u1v - u0v);
            }

#pragma unroll
            for (int stage = 0; stage < 6; ++stage) {
                // ---- owner: build z x-part (kk already in registers) ----
                {
                    float xs;
                    switch (stage) {
                    case 0: xs = xc; break;
                    case 1: xs = xc + dt * (A21 * kk[0]); break;
                    case 2: xs = xc + dt * (A31 * kk[0] + A32 * kk[1]); break;
                    case 3: xs = xc + dt * (A41 * kk[0] + A42 * kk[1]
                                          + A43 * kk[2]); break;
                    case 4: xs = xc + dt * (A51 * kk[0] + A52 * kk[1]
                                          + A53 * kk[2] + A54 * kk[3]); break;
                    default: xs = xc + dt * (A61 * kk[0] + A62 * kk[1]
                                           + A63 * kk[2] + A64 * kk[3]
                                           + A65 * kk[4]); break;
                    }
                    zbuf[stage * ZSTRIDE + orr * ZZ + dcol] = xs;
                }
                __syncthreads();   // BAR 1: z (x+u) complete

                // ---- layer 1: pair-split K dot, shfl-combine, tanh -> hbuf ----
                {
                    const float* zs = zbuf + stage * ZSTRIDE + half * 36;
                    float hv[ROWS];
#pragma unroll
                    for (int rr = 0; rr < ROWS; ++rr) {
                        const ulonglong2* zr =
                            reinterpret_cast<const ulonglong2*>(zs + rr * ZZ);
                        u64 a0 = 0ull, a1 = 0ull;
#pragma unroll
                        for (int i = 0; i < 9; ++i) {   // 9 LDS.128, 18 FMA2
                            ulonglong2 zz = zr[i];
                            a0 = fma2(zz.x, w1p[2 * i],     a0);
                            a1 = fma2(zz.y, w1p[2 * i + 1], a1);
                        }
                        float2 f0 = unpack2(a0), f1 = unpack2(a1);
                        float p = (f0.x + f0.y) + (f1.x + f1.y) + b1j;
                        hv[rr] = p + __shfl_xor_sync(0xffffffffu, p, 1);
                    }
                    // even lane stores rows 0-3, odd lane rows 4-7
                    const int skj = j + ((j >> 5) << 2);
#pragma unroll
                    for (int q = 0; q < 4; ++q) {
                        int rr = half * 4 + q;
                        hbuf[rr * HSTRIDE + skj] = fast_tanh(hv[rr]);
                    }
                }
                __syncthreads();   // BAR 2: h complete

                // ---- layer 2: 32-K slice dots + 3-step butterfly (in-warp) ----
                {
                    float tot[ROWS];
#pragma unroll
                    for (int rr = 0; rr < ROWS; ++rr) {
                        const ulonglong2* hr = reinterpret_cast<const ulonglong2*>(
                            hbuf + rr * HSTRIDE + pg * 36);
                        u64 a0 = 0ull, a1 = 0ull;
#pragma unroll
                        for (int i = 0; i < 8; ++i) {   // 8 LDS.128, 16 FMA2
                            ulonglong2 hh = hr[i];
                            a0 = fma2(hh.x, w2p[2 * i],     a0);
                            a1 = fma2(hh.y, w2p[2 * i + 1], a1);
                        }
                        float2 f0 = unpack2(a0), f1 = unpack2(a1);
                        tot[rr] = (f0.x + f0.y) + (f1.x + f1.y);
                    }
#pragma unroll
                    for (int rr = 0; rr < ROWS; ++rr) {
                        tot[rr] += __shfl_xor_sync(0xffffffffu, tot[rr], 1);
                        tot[rr] += __shfl_xor_sync(0xffffffffu, tot[rr], 2);
                        tot[rr] += __shfl_xor_sync(0xffffffffu, tot[rr], 4);
                    }
                    kk[stage] = tot[orr] + b2d;
                }
                // no barrier: next zbuild writes zbuf (all readers passed BAR2),
                // next layer1 hbuf writes are behind next BAR1.
            } // stages

            // ---- advance x ----
            {
                float xn = xc + dt * (B1 * kk[0] + B3 * kk[2]
                                    + B4 * kk[3] + B5 * kk[4] + B6 * kk[5]);
                xc = xn;
                if (s == NSUB - 1)
                    out[(size_t)(b0 + orr) * (TT * DD) + (ci + 1) * DD + dcol] = xn;
            }
        }
    }
}

extern "C" void kernel_launch(void* const* d_in, const int* in_sizes, int n_in,
                              void* d_out, int out_size) {
    const float* x0 = (const float*)d_in[0];
    const float* te = (const float*)d_in[1];
    const float* tu = (const float*)d_in[2];
    const float* ub = (const float*)d_in[3];
    const float* W1 = (const float*)d_in[4];
    const float* b1 = (const float*)d_in[5];
    const float* W2 = (const float*)d_in[6];
    const float* b2 = (const float*)d_in[7];
    float* out = (float*)d_out;

    const int smem_bytes = SMEM_FLOATS * (int)sizeof(float);
    cudaFuncSetAttribute(node_kernel,
                         cudaFuncAttributeMaxDynamicSharedMemorySize, smem_bytes);
    node_kernel<<<CTAS, NT, smem_bytes>>>(x0, te, tu, ub, W1, b1, W2, b2, out);
}

// round 5
// speedup vs baseline: 1.7177x; 1.7177x over previous
#include <cuda_runtime.h>

#define DD 64
#define FF 8
#define ZZ 72          // D + F
#define HH 256
#define TT 50
#define TUU 128
#define CTAS 128
#define NT 512

typedef unsigned long long u64;

__device__ __forceinline__ u64 fma2(u64 a, u64 b, u64 c) {
    u64 d;
    asm("fma.rn.f32x2 %0, %1, %2, %3;" : "=l"(d) : "l"(a), "l"(b), "l"(c));
    return d;
}
__device__ __forceinline__ u64 pack2(float lo, float hi) {
    u64 d;
    asm("mov.b64 %0, {%1, %2};" : "=l"(d) : "f"(lo), "f"(hi));
    return d;
}
__device__ __forceinline__ float2 unpack2(u64 v) {
    float lo, hi;
    asm("mov.b64 {%0, %1}, %2;" : "=f"(lo), "=f"(hi) : "l"(v));
    return make_float2(lo, hi);
}
// tanh(x) = 1 - 2/(exp(2x)+1) via ex2.approx + rcp.approx, abs err ~1e-6.
__device__ __forceinline__ float fast_tanh(float x) {
    float e, r;
    asm("ex2.approx.f32 %0, %1;" : "=f"(e) : "f"(x * 2.8853900817779268f));
    asm("rcp.approx.f32 %0, %1;" : "=f"(r) : "f"(e + 1.0f));
    return fmaf(-2.0f, r, 1.0f);
}

// Named barriers (ids 1..6; id 0 reserved for __syncthreads):
//   1+G : zready[G]  (L2 arrives 256, L1 syncs 256; count 512)
//   3+G : hready[G]  (L1 arrives 256, L2 syncs 256; count 512)
//   5   : L1-internal combine barrier (count 256)
//   6   : L2-internal partial barrier (count 256)
#define BSYNC(id, cnt) asm volatile("bar.sync %0, %1;"   :: "r"(id), "n"(cnt) : "memory")
#define BARV(id, cnt)  asm volatile("bar.arrive %0, %1;" :: "r"(id), "n"(cnt) : "memory")

// SMEM floats:
//   ubuf 8192 | zbuf 2*4*72=576 | hbuf 2*4*256=2048 | p1 1024 | p2 2048 | te 64 | tu 128
#define SMEM_FLOATS (8192 + 576 + 2048 + 1024 + 2048 + 64 + 128)

__device__ __forceinline__ void u_interp(float* zG, const float* tu,
                                         const float* ub, int G, int i2,
                                         float tst) {
    // exact jnp.searchsorted(side='right')-1 semantics
    int r = i2 >> 3, f = i2 & 7;
    int idx = (int)floorf(tst * (float)(TUU - 1));
    idx = max(0, min(TUU - 2, idx));
    while (idx > 0 && tu[idx] > tst) --idx;
    while (idx < TUU - 2 && tu[idx + 1] <= tst) ++idx;
    float t0 = tu[idx], t1 = tu[idx + 1];
    float w = (tst - t0) / (t1 - t0);
    const float* ur = ub + (G * 4 + r) * (TUU * FF);
    float u0 = ur[idx * FF + f], u1 = ur[(idx + 1) * FF + f];
    zG[r * ZZ + DD + f] = u0 + w * (u1 - u0);
}

__global__ void __launch_bounds__(NT, 1)
node_kernel(const float* __restrict__ x0g, const float* __restrict__ te_g,
            const float* __restrict__ tu_g, const float* __restrict__ u_g,
            const float* __restrict__ W1g, const float* __restrict__ b1g,
            const float* __restrict__ W2g, const float* __restrict__ b2g,
            float* __restrict__ out)
{
    extern __shared__ float sm[];
    float* ubuf = sm;                  // [8][TUU][FF]
    float* zbuf = ubuf + 8192;         // [2][4][ZZ]
    float* hbuf = zbuf + 576;          // [2][4][HH]
    float* p1   = hbuf + 2048;         // [4][256] layer-1 partials
    float* p2   = p1 + 1024;           // [4][8][64] layer-2 partials
    float* te   = p2 + 2048;           // [64]
    float* tu   = te + 64;             // [TUU]
    u64* p1q = reinterpret_cast<u64*>(p1);
    u64* p2q = reinterpret_cast<u64*>(p2);
    u64* hq  = reinterpret_cast<u64*>(hbuf);

    const int tid = threadIdx.x;
    const int b0  = blockIdx.x * 8;

    // ---- one-time smem loads (all threads) ----
    for (int i = tid; i < TT;  i += NT) te[i] = te_g[i];
    for (int i = tid; i < TUU; i += NT) tu[i] = tu_g[i];
    for (int i = tid; i < 8 * TUU * FF; i += NT) {
        int r = i / (TUU * FF);
        int o = i - r * (TUU * FF);
        ubuf[i] = u_g[(size_t)(b0 + r) * (TUU * FF) + o];
    }

    // Dopri5 tableau (fp32-rounded)
    const float A21 = 0.2f;
    const float A31 = 0.075f,                    A32 = 0.225f;
    const float A41 = (float)( 44.0/45.0),       A42 = (float)(-56.0/15.0),
                A43 = (float)( 32.0/9.0);
    const float A51 = (float)( 19372.0/6561.0),  A52 = (float)(-25360.0/2187.0),
                A53 = (float)( 64448.0/6561.0),  A54 = (float)(-212.0/729.0);
    const float A61 = (float)( 9017.0/3168.0),   A62 = (float)(-355.0/33.0),
                A63 = (float)( 46732.0/5247.0),  A64 = (float)( 49.0/176.0),
                A65 = (float)(-5103.0/18656.0);
    const float B1  = (float)( 35.0/384.0),      B3  = (float)(500.0/1113.0),
                B4  = (float)(125.0/192.0),      B5  = (float)(-2187.0/6784.0),
                B6  = (float)( 11.0/84.0);

    if (tid < 256) {
        // ================= LAYER-1 WORKERS (warps 0-7) =================
        // thread (half, t): columns j0=2t, j1=2t+1; K-range [half*36, +36)
        const int half = tid >> 7;
        const int t    = tid & 127;
        const int j0   = 2 * t;
        u64 w1a[18], w1b[18];
#pragma unroll
        for (int i = 0; i < 18; ++i) {
            int k = half * 36 + 2 * i;
            w1a[i] = pack2(W1g[k * HH + j0],     W1g[(k + 1) * HH + j0]);
            w1b[i] = pack2(W1g[k * HH + j0 + 1], W1g[(k + 1) * HH + j0 + 1]);
        }
        const float b10 = b1g[j0], b11 = b1g[j0 + 1];
        const int dr = half ? 0 : 2;   // rows donated to partner
        const int mr = half ? 2 : 0;   // rows combined by me

        __syncthreads();               // init complete

        for (int m = 0; m < 196; ++m) {
#pragma unroll
            for (int st = 0; st < 6; ++st) {
#pragma unroll
                for (int G = 0; G < 2; ++G) {
                    BSYNC(1 + G, 512);                 // wait z(G) ready
                    const float* zb = zbuf + G * 288 + half * 36;
                    float pr0[4], pr1[4];
#pragma unroll
                    for (int r = 0; r < 4; ++r) {
                        const ulonglong2* zr =
                            reinterpret_cast<const ulonglong2*>(zb + r * ZZ);
                        u64 a0 = 0ull, a1 = 0ull, c0 = 0ull, c1 = 0ull;
#pragma unroll
                        for (int i = 0; i < 9; ++i) {  // 9 LDS.128, 36 FMA2
                            ulonglong2 zz = zr[i];
                            a0 = fma2(zz.x, w1a[2 * i],     a0);
                            a1 = fma2(zz.y, w1a[2 * i + 1], a1);
                            c0 = fma2(zz.x, w1b[2 * i],     c0);
                            c1 = fma2(zz.y, w1b[2 * i + 1], c1);
                        }
                        float2 fa = unpack2(a0), fb = unpack2(a1);
                        float2 fc = unpack2(c0), fd = unpack2(c1);
                        pr0[r] = (fa.x + fa.y) + (fb.x + fb.y);
                        pr1[r] = (fc.x + fc.y) + (fd.x + fd.y);
                    }
                    // donate partner's rows
                    p1q[dr * 128 + t]       = pack2(pr0[dr],     pr1[dr]);
                    p1q[(dr + 1) * 128 + t] = pack2(pr0[dr + 1], pr1[dr + 1]);
                    BSYNC(5, 256);                     // L1-internal
                    // combine my rows + tanh -> hbuf
#pragma unroll
                    for (int q = 0; q < 2; ++q) {
                        int r = mr + q;
                        float2 pp = unpack2(p1q[r * 128 + t]);
                        float h0 = fast_tanh(pr0[r] + pp.x + b10);
                        float h1 = fast_tanh(pr1[r] + pp.y + b11);
                        hq[G * 512 + r * 128 + t] = pack2(h0, h1);
                    }
                    BARV(3 + G, 512);                  // h(G) ready
                }
            }
        }
    } else {
        // ================= LAYER-2 WORKERS (warps 8-15) =================
        // thread (pg, dp): columns c0=2dp, c1=2dp+1; K-slice [pg*32, +32).
        // Owner of state element (er = pg&3, edc = 2dp + (pg>>2)) per group.
        const int i2 = tid - 256;
        const int pg = i2 >> 5;
        const int dp = i2 & 31;
        const int c0 = 2 * dp;
        const int er  = pg & 3;
        const int edc = c0 + (pg >> 2);
        u64 w2a[16], w2b[16];
#pragma unroll
        for (int i = 0; i < 16; ++i) {
            int k = pg * 32 + 2 * i;
            w2a[i] = pack2(W2g[k * DD + c0],     W2g[(k + 1) * DD + c0]);
            w2b[i] = pack2(W2g[k * DD + c0 + 1], W2g[(k + 1) * DD + c0 + 1]);
        }
        const float b2d = b2g[edc];
        float xc[2], kk[2][6];
#pragma unroll
        for (int G = 0; G < 2; ++G) {
            int grow = b0 + G * 4 + er;
            xc[G] = x0g[(size_t)grow * DD + edc];
            out[(size_t)grow * (TT * DD) + edc] = xc[G];   // t index 0
        }

        __syncthreads();               // init complete (ubuf/te/tu visible)

        // prologue: z for stage 0 of substep 0, both groups
#pragma unroll
        for (int G = 0; G < 2; ++G) {
            zbuf[G * 288 + er * ZZ + edc] = xc[G];
            if (i2 < 32) u_interp(zbuf + G * 288, tu, ubuf, G, i2, te[0]);
            BARV(1 + G, 512);
        }

        for (int m = 0; m < 196; ++m) {
            const int ci = m >> 2, s = m & 3;
            const float tc0 = te[ci];
            const float dtc = te[ci + 1] - tc0;
            const float dt  = dtc * 0.25f;
            const float tsub = tc0 + dtc * ((float)s * 0.25f);
#pragma unroll
            for (int st = 0; st < 6; ++st) {
#pragma unroll
                for (int G = 0; G < 2; ++G) {
                    BSYNC(3 + G, 512);                 // wait h(G)
                    const float* hb = hbuf + G * 1024 + pg * 32;
#pragma unroll
                    for (int r = 0; r < 4; ++r) {
                        const ulonglong2* hr =
                            reinterpret_cast<const ulonglong2*>(hb + r * HH);
                        u64 a0 = 0ull, a1 = 0ull, d0 = 0ull, d1 = 0ull;
#pragma unroll
                        for (int i = 0; i < 8; ++i) {  // 8 LDS.128, 32 FMA2
                            ulonglong2 hh = hr[i];
                            a0 = fma2(hh.x, w2a[2 * i],     a0);
                            a1 = fma2(hh.y, w2a[2 * i + 1], a1);
                            d0 = fma2(hh.x, w2b[2 * i],     d0);
                            d1 = fma2(hh.y, w2b[2 * i + 1], d1);
                        }
                        float2 fa = unpack2(a0), fb = unpack2(a1);
                        float2 fc = unpack2(d0), fd = unpack2(d1);
                        float s0 = (fa.x + fa.y) + (fb.x + fb.y);
                        float s1 = (fc.x + fc.y) + (fd.x + fd.y);
                        p2q[r * 256 + pg * 32 + dp] = pack2(s0, s1);
                    }
                    BSYNC(6, 256);                     // L2-internal
                    // owner: reduce 8 K-slices for my element
                    const float* pe = p2 + er * 512 + edc;
                    float kv = b2d;
#pragma unroll
                    for (int pgi = 0; pgi < 8; ++pgi) kv += pe[pgi * 64];
                    kk[G][st] = kv;

                    float* zG = zbuf + G * 288;
                    if (st < 5) {
                        float xs;
                        switch (st) {
                        case 0: xs = xc[G] + dt * (A21 * kk[G][0]); break;
                        case 1: xs = xc[G] + dt * (A31 * kk[G][0] + A32 * kk[G][1]); break;
                        case 2: xs = xc[G] + dt * (A41 * kk[G][0] + A42 * kk[G][1]
                                                 + A43 * kk[G][2]); break;
                        case 3: xs = xc[G] + dt * (A51 * kk[G][0] + A52 * kk[G][1]
                                                 + A53 * kk[G][2] + A54 * kk[G][3]); break;
                        default: xs = xc[G] + dt * (A61 * kk[G][0] + A62 * kk[G][1]
                                                  + A63 * kk[G][2] + A64 * kk[G][3]
                                                  + A65 * kk[G][4]); break;
                        }
                        zG[er * ZZ + edc] = xs;
                        if (i2 < 32) {
                            const float CSTN[5] = {0.2f, 0.3f, 0.8f,
                                                   (float)(8.0/9.0), 1.0f};
                            u_interp(zG, tu, ubuf, G, i2, tsub + CSTN[st] * dt);
                        }
                        BARV(1 + G, 512);              // z(G) ready
                    } else {
                        float xn = xc[G] + dt * (B1 * kk[G][0] + B3 * kk[G][2]
                                               + B4 * kk[G][3] + B5 * kk[G][4]
                                               + B6 * kv);
                        xc[G] = xn;
                        if (s == 3)
                            out[(size_t)(b0 + G * 4 + er) * (TT * DD)
                                + (ci + 1) * DD + edc] = xn;
                        if (m < 195) {
                            zG[er * ZZ + edc] = xn;
                            float tn = (s < 3)
                                ? tc0 + dtc * ((float)(s + 1) * 0.25f)
                                : te[ci + 1];
                            if (i2 < 32) u_interp(zG, tu, ubuf, G, i2, tn);
                            BARV(1 + G, 512);          // z(G) ready
                        }
                    }
                }
            }
        }
    }
}

extern "C" void kernel_launch(void* const* d_in, const int* in_sizes, int n_in,
                              void* d_out, int out_size) {
    const float* x0 = (const float*)d_in[0];
    const float* te = (const float*)d_in[1];
    const float* tu = (const float*)d_in[2];
    const float* ub = (const float*)d_in[3];
    const float* W1 = (const float*)d_in[4];
    const float* b1 = (const float*)d_in[5];
    const float* W2 = (const float*)d_in[6];
    const float* b2 = (const float*)d_in[7];
    float* out = (float*)d_out;

    const int smem_bytes = SMEM_FLOATS * (int)sizeof(float);   // 56320 B
    cudaFuncSetAttribute(node_kernel,
                         cudaFuncAttributeMaxDynamicSharedMemorySize, smem_bytes);
    node_kernel<<<CTAS, NT, smem_bytes>>>(x0, te, tu, ub, W1, b1, W2, b2, out);
}